// round 15
// baseline (speedup 1.0000x reference)
#include <cuda_runtime.h>
#include <cuda_bf16.h>
#include <math.h>
#include <stdint.h>

// ---------------- problem constants ----------------
#define Bt   8
#define Nt   384
#define Dt   512
#define Ht   8
#define DEt  32
#define DFt  2048
#define DKt  64
#define BNr  (Bt*Nt)            // 3072
#define NNt  (Nt*Nt)            // 147456

// scratch layout (floats)
#define OFF_NX     0LL
#define OFF_QKV    (OFF_NX    + (long long)BNr*Dt)
#define OFF_ATTN   (OFF_QKV   + (long long)BNr*3*Dt)
#define OFF_CAT    (OFF_ATTN  + (long long)Bt*Ht*NNt)   // [BNr][768] = [ctx | raw]
#define OFF_X1     (OFF_CAT   + (long long)BNr*768)
#define OFF_NX2    (OFF_X1    + (long long)BNr*Dt)
#define OFF_H1     (OFF_NX2   + (long long)BNr*Dt)
#define OFF_WQKV   (OFF_H1    + (long long)BNr*DFt)
#define OFF_BQKV   (OFF_WQKV  + (long long)Dt*3*Dt)
#define OFF_WFOLD  (OFF_BQKV  + 3*Dt)
#define OFF_WCAT   (OFF_WFOLD + (long long)Ht*DEt*Dt)   // [768][512]
#define OFF_BCOMB  (OFF_WCAT  + (long long)768*Dt)
#define OFF_W1T    (OFF_BCOMB + Dt)
#define OFF_W2T    (OFF_W1T   + (long long)Dt*DFt)
#define SCRATCH_TOTAL (OFF_W2T + (long long)DFt*Dt)

static __device__ float g_scratch[SCRATCH_TOTAL];

// ---------------- helpers ----------------
__device__ __forceinline__ float gelu_f(float v) {
    float t3 = v * v * v;
    return 0.5f * v * (1.0f + tanhf(0.7978845608028654f * (v + 0.044715f * t3)));
}

__device__ __forceinline__ float f2tf(float x) {
    uint32_t u;
    asm("cvt.rna.tf32.f32 %0, %1;" : "=r"(u) : "f"(x));
    return __uint_as_float(u);
}

__device__ __forceinline__ void mma_tf32(float* c, const uint32_t* a, const uint32_t* b) {
    asm volatile(
        "mma.sync.aligned.m16n8k8.row.col.f32.tf32.tf32.f32 "
        "{%0,%1,%2,%3}, {%4,%5,%6,%7}, {%8,%9}, {%0,%1,%2,%3};\n"
        : "+f"(c[0]), "+f"(c[1]), "+f"(c[2]), "+f"(c[3])
        : "r"(a[0]), "r"(a[1]), "r"(a[2]), "r"(a[3]), "r"(b[0]), "r"(b[1]));
}

__device__ __forceinline__ void cp_async16(float* smem_dst, const float* gmem_src) {
    uint32_t sa = (uint32_t)__cvta_generic_to_shared(smem_dst);
    asm volatile("cp.async.cg.shared.global [%0], [%1], 16;\n" :: "r"(sa), "l"(gmem_src));
}
__device__ __forceinline__ void cp_commit() {
    asm volatile("cp.async.commit_group;\n" ::: "memory");
}
template<int N>
__device__ __forceinline__ void cp_wait() {
    asm volatile("cp.async.wait_group %0;\n" :: "n"(N) : "memory");
}

__device__ __forceinline__ float blockReduce128(float v, bool isMax, float* sh) {
    #pragma unroll
    for (int o = 16; o; o >>= 1) {
        float o2 = __shfl_xor_sync(0xffffffffu, v, o);
        v = isMax ? fmaxf(v, o2) : v + o2;
    }
    __syncthreads();
    if ((threadIdx.x & 31) == 0) sh[threadIdx.x >> 5] = v;
    __syncthreads();
    float r = sh[0];
    #pragma unroll
    for (int k = 1; k < 4; k++) r = isMax ? fmaxf(r, sh[k]) : r + sh[k];
    return r;
}

// ---------------- LayerNorm over 512 cols (optionally tf32-rounded out) ----------------
__global__ __launch_bounds__(128) void ln512_kernel(
    const float* __restrict__ in, const float* __restrict__ g,
    const float* __restrict__ b, float* __restrict__ out, int round_out)
{
    __shared__ float sh[4];
    int row = blockIdx.x;
    int t = threadIdx.x;
    const float4* inr = (const float4*)(in + (size_t)row * Dt);
    float4 v = inr[t];
    float s  = v.x + v.y + v.z + v.w;
    float sq = v.x*v.x + v.y*v.y + v.z*v.z + v.w*v.w;
    float tot = blockReduce128(s, false, sh);
    __syncthreads();
    float totq = blockReduce128(sq, false, sh);
    float mean = tot * (1.0f / Dt);
    float var  = totq * (1.0f / Dt) - mean * mean;
    float inv  = rsqrtf(var + 1e-5f);
    float4 gg = ((const float4*)g)[t];
    float4 bb = ((const float4*)b)[t];
    float4 o;
    o.x = (v.x - mean) * inv * gg.x + bb.x;
    o.y = (v.y - mean) * inv * gg.y + bb.y;
    o.z = (v.z - mean) * inv * gg.z + bb.z;
    o.w = (v.w - mean) * inv * gg.w + bb.w;
    if (round_out) {
        o.x = f2tf(o.x); o.y = f2tf(o.y); o.z = f2tf(o.z); o.w = f2tf(o.w);
    }
    ((float4*)(out + (size_t)row * Dt))[t] = o;
}

// ---------------- merged preproc ----------------
__global__ __launch_bounds__(256) void preproc_kernel(
    const float* __restrict__ Wq, const float* __restrict__ Wk,
    const float* __restrict__ Wv,
    const float* __restrict__ bq, const float* __restrict__ bk,
    const float* __restrict__ bv,
    const float* __restrict__ Wo, const float* __restrict__ bo,
    const float* __restrict__ Wke, const float* __restrict__ bke,
    const float* __restrict__ Weo, const float* __restrict__ beo,
    const float* __restrict__ W1, const float* __restrict__ W2,
    float* __restrict__ Wqkv, float* __restrict__ bqkv,
    float* __restrict__ Wcat, float* __restrict__ Wfold,
    float* __restrict__ bcomb,
    float* __restrict__ W1t, float* __restrict__ W2t)
{
    int bx = blockIdx.x;
    int t = threadIdx.x;

    if (bx < 512) {
        int k = bx;
        for (int n = t; n < Dt; n += 256) {
            Wqkv[(size_t)k * 1536 + n]        = f2tf(Wq[(size_t)k * Dt + n]);
            Wqkv[(size_t)k * 1536 + 512 + n]  = f2tf(Wk[(size_t)k * Dt + n]);
            Wqkv[(size_t)k * 1536 + 1024 + n] = f2tf(Wv[(size_t)k * Dt + n]);
            Wcat[(size_t)k * Dt + n]          = f2tf(Wo[(size_t)k * Dt + n]);
        }
        for (int n = t; n < DFt; n += 256)
            W1t[(size_t)k * DFt + n] = f2tf(W1[(size_t)k * DFt + n]);
        #pragma unroll
        for (int r = 0; r < 4; r++) {
            int row = k * 4 + r;
            for (int n = t; n < Dt; n += 256)
                W2t[(size_t)row * Dt + n] = f2tf(W2[(size_t)row * Dt + n]);
        }
        if (k == 0) {
            for (int n = t; n < Dt; n += 256) {
                bqkv[n] = bq[n]; bqkv[512 + n] = bk[n]; bqkv[1024 + n] = bv[n];
            }
        }
    } else if (bx < 528) {
        __shared__ float sK[32 * 32];
        int idx = bx - 512;
        int h = idx >> 1;
        int d = (idx & 1) * 256 + t;
        for (int i = t; i < 1024; i += 256) sK[i] = Wke[i];
        __syncthreads();
        float wcol[32];
        #pragma unroll
        for (int c = 0; c < 32; c++)
            wcol[c] = Weo[(size_t)(h * 32 + c) * Dt + d];
        for (int k = 0; k < 32; k++) {
            float acc = 0.0f;
            #pragma unroll
            for (int c = 0; c < 32; c++) acc += sK[k * 32 + c] * wcol[c];
            Wfold[(size_t)(h * 32 + k) * Dt + d] = acc;
        }
    } else if (bx < 544) {
        __shared__ float sbf[Dt];
        __shared__ float red[8][33];
        int lane = t & 31, w = t >> 5;
        #pragma unroll
        for (int rr = 0; rr < 2; rr++) {
            int d = t + rr * 256;
            float acc = beo[d];
            for (int e = 0; e < Ht * DEt; e++)
                acc += bke[e & 31] * Weo[(size_t)e * Dt + d];
            sbf[d] = acc;
        }
        __syncthreads();
        int out = (bx - 528) * 32 + lane;
        float acc = 0.0f;
        for (int e = w; e < Dt; e += 8)
            acc += sbf[e] * Wo[(size_t)(Dt + e) * Dt + out];
        red[w][lane] = acc;
        __syncthreads();
        if (w == 0) {
            float s = bo[out];
            #pragma unroll
            for (int k = 0; k < 8; k++) s += red[k][lane];
            bcomb[out] = s;
        }
    } else {
        float4* dst = (float4*)(Wcat + (size_t)Dt * Dt);
        int base = (bx - 544) * 1024 + t;
        #pragma unroll
        for (int rr = 0; rr < 4; rr++)
            dst[base + rr * 256] = make_float4(0.f, 0.f, 0.f, 0.f);
    }
}

// ---------------- tf32 tensor-core GEMM ----------------
// CVT=false: cp.async 3-stage pipeline, one sync per K-iter (operands pre-rounded).
// CVT=true : LDG->reg->cvt->STS 2-stage path.
// accumulate: 0=store,1=read-add,2=atomicAdd. round_out: tf32-round epilogue.
template<int TBM, int TBN, int WM, int WN, bool TRANSB, bool CVT>
__global__ __launch_bounds__(256, 1) void gemm_tf32_kernel(
    const float* __restrict__ A, const float* __restrict__ Bm, float* __restrict__ C,
    int K, int lda, int ldb, int ldc,
    int batch2,
    long long sA1, long long sA2, long long sB1, long long sB2,
    long long sC1, long long sC2,
    float alpha, const float* __restrict__ bias,
    const float* __restrict__ addend, int ldadd,
    int accumulate, int act_gelu, int round_out)
{
    constexpr int BK = 32;
    constexpr int WNC = TBN / WN;
    constexpr int MF = WM / 16;
    constexpr int NF = WN / 8;
    constexpr int LDA_S = BK + 4;
    constexpr int LDB_S = TRANSB ? (BK + 4) : (TBN + 8);
    constexpr int BS_ROWS = TRANSB ? TBN : BK;
    constexpr int A_IT = TBM / 32;
    constexpr int B_IT = TRANSB ? (TBN / 32) : ((BK * TBN) / 1024);
    constexpr int NSTAGE = CVT ? 2 : 3;
    constexpr int A_STG = TBM * LDA_S;
    constexpr int B_STG = BS_ROWS * LDB_S;

    extern __shared__ float smem[];
    float* As = smem;
    float* Bs = smem + NSTAGE * A_STG;

    int z = blockIdx.z;
    int z1 = z / batch2, z2 = z % batch2;
    A  += z1 * sA1 + z2 * sA2;
    Bm += z1 * sB1 + z2 * sB2;
    C  += z1 * sC1 + z2 * sC2;

    const int m_blk = blockIdx.y * TBM;
    const int n_blk = blockIdx.x * TBN;

    const int tid = threadIdx.x;
    const int warp = tid >> 5, lane = tid & 31;
    const int g = lane >> 2, tig = lane & 3;
    const int wm = warp / WNC, wn = warp % WNC;
    const int m0 = wm * WM, n0 = wn * WN;

    auto computeStage = [&](int s, float acc[MF][NF][4]) {
        #pragma unroll
        for (int ks = 0; ks < 4; ks++) {
            int kb = ks * 8;
            uint32_t afr[MF][4], bfr[NF][2];
            #pragma unroll
            for (int i = 0; i < MF; i++) {
                const float* ap = &As[(size_t)s * A_STG + (m0 + i * 16) * LDA_S + kb];
                afr[i][0] = __float_as_uint(ap[(size_t)g * LDA_S + tig]);
                afr[i][1] = __float_as_uint(ap[(size_t)(g + 8) * LDA_S + tig]);
                afr[i][2] = __float_as_uint(ap[(size_t)g * LDA_S + tig + 4]);
                afr[i][3] = __float_as_uint(ap[(size_t)(g + 8) * LDA_S + tig + 4]);
            }
            #pragma unroll
            for (int j = 0; j < NF; j++) {
                if (TRANSB) {
                    const float* bp = &Bs[(size_t)s * B_STG + (n0 + j * 8 + g) * LDB_S + kb];
                    bfr[j][0] = __float_as_uint(bp[tig]);
                    bfr[j][1] = __float_as_uint(bp[tig + 4]);
                } else {
                    const float* bp = &Bs[(size_t)s * B_STG + kb * LDB_S + n0 + j * 8 + g];
                    bfr[j][0] = __float_as_uint(bp[(size_t)tig * LDB_S]);
                    bfr[j][1] = __float_as_uint(bp[(size_t)(tig + 4) * LDB_S]);
                }
            }
            #pragma unroll
            for (int i = 0; i < MF; i++)
                #pragma unroll
                for (int j = 0; j < NF; j++)
                    mma_tf32(acc[i][j], afr[i], bfr[j]);
        }
    };

    float acc[MF][NF][4];
    #pragma unroll
    for (int i = 0; i < MF; i++)
        #pragma unroll
        for (int j = 0; j < NF; j++)
            #pragma unroll
            for (int q = 0; q < 4; q++) acc[i][j][q] = 0.0f;

    const int nk = K / BK;

    if constexpr (!CVT) {
        auto issueStage = [&](int s, int k0) {
            #pragma unroll
            for (int it = 0; it < A_IT; it++) {
                int idx = tid + it * 256;
                int r = idx >> 3, kq = (idx & 7) << 2;
                cp_async16(&As[(size_t)s * A_STG + r * LDA_S + kq],
                           &A[(size_t)(m_blk + r) * lda + k0 + kq]);
            }
            #pragma unroll
            for (int it = 0; it < B_IT; it++) {
                int idx = tid + it * 256;
                if (TRANSB) {
                    int r = idx >> 3, kq = (idx & 7) << 2;
                    cp_async16(&Bs[(size_t)s * B_STG + r * LDB_S + kq],
                               &Bm[(size_t)(n_blk + r) * ldb + k0 + kq]);
                } else {
                    int r = idx / (TBN / 4), c = (idx % (TBN / 4)) << 2;
                    cp_async16(&Bs[(size_t)s * B_STG + r * LDB_S + c],
                               &Bm[(size_t)(k0 + r) * ldb + n_blk + c]);
                }
            }
        };

        issueStage(0, 0); cp_commit();
        issueStage(1, BK); cp_commit();          // nk >= 2 for all call sites

        for (int kt = 0; kt < nk; kt++) {
            if (kt < nk - 1) cp_wait<1>(); else cp_wait<0>();
            __syncthreads();
            if (kt + 2 < nk) { issueStage((kt + 2) % 3, (kt + 2) * BK); cp_commit(); }
            computeStage(kt % 3, acc);
        }
    } else {
        float4 ra2[A_IT], rb2[B_IT];
        auto loadA2 = [&](int k0) {
            #pragma unroll
            for (int it = 0; it < A_IT; it++) {
                int idx = tid + it * 256;
                int r = idx >> 3, kq = (idx & 7) << 2;
                ra2[it] = *(const float4*)&A[(size_t)(m_blk + r) * lda + k0 + kq];
            }
        };
        auto storeA2 = [&](int s) {
            #pragma unroll
            for (int it = 0; it < A_IT; it++) {
                int idx = tid + it * 256;
                int r = idx >> 3, kq = (idx & 7) << 2;
                float4 v = ra2[it];
                v.x = f2tf(v.x); v.y = f2tf(v.y); v.z = f2tf(v.z); v.w = f2tf(v.w);
                *(float4*)&As[(size_t)s * A_STG + r * LDA_S + kq] = v;
            }
        };
        auto loadB2 = [&](int k0) {
            #pragma unroll
            for (int it = 0; it < B_IT; it++) {
                int idx = tid + it * 256;
                if (TRANSB) {
                    int r = idx >> 3, kq = (idx & 7) << 2;
                    rb2[it] = *(const float4*)&Bm[(size_t)(n_blk + r) * ldb + k0 + kq];
                } else {
                    int r = idx / (TBN / 4), c = (idx % (TBN / 4)) << 2;
                    rb2[it] = *(const float4*)&Bm[(size_t)(k0 + r) * ldb + n_blk + c];
                }
            }
        };
        auto storeB2 = [&](int s) {
            #pragma unroll
            for (int it = 0; it < B_IT; it++) {
                int idx = tid + it * 256;
                float4 v = rb2[it];
                v.x = f2tf(v.x); v.y = f2tf(v.y); v.z = f2tf(v.z); v.w = f2tf(v.w);
                if (TRANSB) {
                    int r = idx >> 3, kq = (idx & 7) << 2;
                    *(float4*)&Bs[(size_t)s * B_STG + r * LDB_S + kq] = v;
                } else {
                    int r = idx / (TBN / 4), c = (idx % (TBN / 4)) << 2;
                    *(float4*)&Bs[(size_t)s * B_STG + r * LDB_S + c] = v;
                }
            }
        };

        loadA2(0); loadB2(0);
        storeA2(0); storeB2(0);
        __syncthreads();

        for (int kt = 0; kt < nk; kt++) {
            int s = kt & 1;
            if (kt + 1 < nk) { loadA2((kt + 1) * BK); loadB2((kt + 1) * BK); }
            computeStage(s, acc);
            if (kt + 1 < nk) { storeA2(s ^ 1); storeB2(s ^ 1); }
            __syncthreads();
        }
    }

    #pragma unroll
    for (int i = 0; i < MF; i++) {
        int row0 = m_blk + m0 + i * 16 + g;
        #pragma unroll
        for (int half = 0; half < 2; half++) {
            int row = row0 + half * 8;
            size_t roff = (size_t)row * ldc;
            #pragma unroll
            for (int j = 0; j < NF; j++) {
                int col = n_blk + n0 + j * 8 + tig * 2;
                float v0 = acc[i][j][half * 2 + 0] * alpha;
                float v1 = acc[i][j][half * 2 + 1] * alpha;
                if (accumulate == 2) {
                    atomicAdd(&C[roff + col], v0);
                    atomicAdd(&C[roff + col + 1], v1);
                    continue;
                }
                if (bias)   { v0 += bias[col]; v1 += bias[col + 1]; }
                if (addend) {
                    const float* ad = &addend[(size_t)row * ldadd + col];
                    v0 += ad[0]; v1 += ad[1];
                }
                if (accumulate == 1) { v0 += C[roff + col]; v1 += C[roff + col + 1]; }
                if (act_gelu)   { v0 = gelu_f(v0); v1 = gelu_f(v1); }
                if (round_out)  { v0 = f2tf(v0); v1 = f2tf(v1); }
                float2 o = make_float2(v0, v1);
                *(float2*)&C[roff + col] = o;
            }
        }
    }
}

// ---------------- fused edge: LN + bias + softmax + ectx contraction ----------------
__global__ __launch_bounds__(256) void edge_attn_kernel(
    float* __restrict__ attn, const float4* __restrict__ edge4,
    const float* __restrict__ eg, const float* __restrict__ eb,
    const float* __restrict__ Web, const float* __restrict__ beb,
    const unsigned char* __restrict__ mask, float* __restrict__ cat)
{
    constexpr int LDAS = 388;
    constexpr int LDBS = 40;
    extern __shared__ float smem[];
    float* sA = smem;
    float* sB = smem + 16 * LDAS;
    float* sbias = sB + Nt * LDBS;

    int bi = blockIdx.x;
    int b = bi / Nt, i = bi % Nt;
    int t = threadIdx.x;
    int l8 = t & 7, rgrp = t >> 3;

    float4 g4 = __ldg(&((const float4*)eg)[l8]);
    float4 b4 = __ldg(&((const float4*)eb)[l8]);
    float4 wb = __ldg(&((const float4*)Web)[l8]);
    float bb = __ldg(beb);

    #pragma unroll
    for (int pp = 0; pp < 12; pp++) {
        int j = pp * 32 + rgrp;
        float4 e = edge4[((long long)bi * Nt + j) * 8 + l8];
        float s = e.x + e.y + e.z + e.w;
        s += __shfl_xor_sync(0xffffffffu, s, 4);
        s += __shfl_xor_sync(0xffffffffu, s, 2);
        s += __shfl_xor_sync(0xffffffffu, s, 1);
        float mean = s * (1.0f / 32.0f);
        float4 d = make_float4(e.x - mean, e.y - mean, e.z - mean, e.w - mean);
        float vq = d.x*d.x + d.y*d.y + d.z*d.z + d.w*d.w;
        vq += __shfl_xor_sync(0xffffffffu, vq, 4);
        vq += __shfl_xor_sync(0xffffffffu, vq, 2);
        vq += __shfl_xor_sync(0xffffffffu, vq, 1);
        float inv = rsqrtf(vq * (1.0f / 32.0f) + 1e-5f);
        float4 ne;
        ne.x = d.x * inv * g4.x + b4.x;
        ne.y = d.y * inv * g4.y + b4.y;
        ne.z = d.z * inv * g4.z + b4.z;
        ne.w = d.w * inv * g4.w + b4.w;
        float pb = ne.x*wb.x + ne.y*wb.y + ne.z*wb.z + ne.w*wb.w;
        pb += __shfl_xor_sync(0xffffffffu, pb, 4);
        pb += __shfl_xor_sync(0xffffffffu, pb, 2);
        pb += __shfl_xor_sync(0xffffffffu, pb, 1);
        if (l8 == 0) sbias[j] = (pb + bb) * 0.70710678118654752f;
        ne.x = f2tf(ne.x); ne.y = f2tf(ne.y);
        ne.z = f2tf(ne.z); ne.w = f2tf(ne.w);
        *(float4*)&sB[j * LDBS + l8 * 4] = ne;
    }
    __syncthreads();

    int warp = t >> 5, lane = t & 31;
    float* sp = attn + (((size_t)(b * Ht + warp)) * Nt + i) * Nt;
    const unsigned char* mp = mask + (size_t)bi * Nt;
    float v[12];
    float mx = -INFINITY;
    #pragma unroll
    for (int r = 0; r < 12; r++) {
        int j = lane + r * 32;
        float s = sp[j] + sbias[j];
        if (mp[j]) s = -INFINITY;
        v[r] = s;
        mx = fmaxf(mx, s);
    }
    #pragma unroll
    for (int o = 16; o; o >>= 1) mx = fmaxf(mx, __shfl_xor_sync(0xffffffffu, mx, o));
    float sum = 0.0f;
    #pragma unroll
    for (int r = 0; r < 12; r++) { v[r] = __expf(v[r] - mx); sum += v[r]; }
    #pragma unroll
    for (int o = 16; o; o >>= 1) sum += __shfl_xor_sync(0xffffffffu, sum, o);
    float invs = 1.0f / sum;
    #pragma unroll
    for (int r = 0; r < 12; r++) {
        int j = lane + r * 32;
        float val = f2tf(v[r] * invs);
        sp[j] = val;
        sA[warp * LDAS + j] = val;
    }
    __syncthreads();

    if (warp < 4) {
        int g = lane >> 2, tig = lane & 3;
        int n0 = warp * 8;
        float acc[4] = {0.0f, 0.0f, 0.0f, 0.0f};
        #pragma unroll
        for (int k8 = 0; k8 < 48; k8++) {
            int kb = k8 * 8;
            uint32_t afr[4], bfr[2];
            afr[0] = __float_as_uint(sA[g * LDAS + kb + tig]);
            afr[1] = __float_as_uint(sA[(g + 8) * LDAS + kb + tig]);
            afr[2] = __float_as_uint(sA[g * LDAS + kb + tig + 4]);
            afr[3] = __float_as_uint(sA[(g + 8) * LDAS + kb + tig + 4]);
            bfr[0] = __float_as_uint(sB[(kb + tig) * LDBS + n0 + g]);
            bfr[1] = __float_as_uint(sB[(kb + tig + 4) * LDBS + n0 + g]);
            mma_tf32(acc, afr, bfr);
        }
        float2 o = make_float2(acc[0], acc[1]);
        *(float2*)&cat[(size_t)bi * 768 + 512 + g * DEt + n0 + tig * 2] = o;
    }
}

// ---------------- launch ----------------
extern "C" void kernel_launch(void* const* d_in, const int* in_sizes, int n_in,
                              void* d_out, int out_size)
{
    const float* x      = (const float*)d_in[0];
    const float* edge   = (const float*)d_in[1];
    const unsigned char* mask = (const unsigned char*)d_in[2];
    const float* ln_a_g = (const float*)d_in[3];
    const float* ln_a_b = (const float*)d_in[4];
    const float* ln_e_g = (const float*)d_in[5];
    const float* ln_e_b = (const float*)d_in[6];
    const float* Wq = (const float*)d_in[7];   const float* bq = (const float*)d_in[8];
    const float* Wk = (const float*)d_in[9];   const float* bk = (const float*)d_in[10];
    const float* Wv = (const float*)d_in[11];  const float* bv = (const float*)d_in[12];
    const float* Wke = (const float*)d_in[13]; const float* bke = (const float*)d_in[14];
    const float* Web = (const float*)d_in[15]; const float* beb = (const float*)d_in[16];
    const float* Weo = (const float*)d_in[17]; const float* beo = (const float*)d_in[18];
    const float* Wo  = (const float*)d_in[19]; const float* bo  = (const float*)d_in[20];
    const float* ln_f_g = (const float*)d_in[21];
    const float* ln_f_b = (const float*)d_in[22];
    const float* W1 = (const float*)d_in[23];  const float* b1 = (const float*)d_in[24];
    const float* W2 = (const float*)d_in[25];  const float* b2 = (const float*)d_in[26];
    float* out = (float*)d_out;

    float* base;
    cudaGetSymbolAddress((void**)&base, g_scratch);
    float* nx    = base + OFF_NX;
    float* qkv   = base + OFF_QKV;
    float* attn  = base + OFF_ATTN;
    float* cat   = base + OFF_CAT;
    float* x1    = base + OFF_X1;
    float* nx2   = base + OFF_NX2;
    float* h1    = base + OFF_H1;
    float* Wqkv  = base + OFF_WQKV;
    float* bqkv  = base + OFF_BQKV;
    float* Wfold = base + OFF_WFOLD;
    float* Wcat  = base + OFF_WCAT;
    float* bcomb = base + OFF_BCOMB;
    float* W1t   = base + OFF_W1T;
    float* W2t   = base + OFF_W2T;

    auto GA  = gemm_tf32_kernel<128, 128, 64, 32, false, false>;
    auto GAC = gemm_tf32_kernel<128, 128, 64, 32, false, true>;
    auto GT  = gemm_tf32_kernel<128, 128, 64, 32, true,  false>;
    auto GV  = gemm_tf32_kernel<128, 64, 32, 32, false, false>;
    auto GS  = gemm_tf32_kernel<64, 64, 16, 32, false, true>;

    constexpr int SMEM_GA = 3 * (128 * 36 + 32 * 136) * 4;    // 107520
    constexpr int SMEM_GAC = 2 * (128 * 36 + 32 * 136) * 4;   // 71680
    constexpr int SMEM_GT = 3 * (128 * 36 + 128 * 36) * 4;    // 110592
    constexpr int SMEM_GV = 3 * (128 * 36 + 32 * 72) * 4;     // 82944
    constexpr int SMEM_GS = 2 * (64 * 36 + 32 * 72) * 4;      // 36864
    constexpr int SMEM_EA = (16 * 388 + 384 * 40 + 384) * 4;  // 87808
    cudaFuncSetAttribute(GA,  cudaFuncAttributeMaxDynamicSharedMemorySize, SMEM_GA);
    cudaFuncSetAttribute(GAC, cudaFuncAttributeMaxDynamicSharedMemorySize, SMEM_GAC);
    cudaFuncSetAttribute(GT,  cudaFuncAttributeMaxDynamicSharedMemorySize, SMEM_GT);
    cudaFuncSetAttribute(GV,  cudaFuncAttributeMaxDynamicSharedMemorySize, SMEM_GV);
    cudaFuncSetAttribute(GS,  cudaFuncAttributeMaxDynamicSharedMemorySize, SMEM_GS);
    cudaFuncSetAttribute(edge_attn_kernel, cudaFuncAttributeMaxDynamicSharedMemorySize, SMEM_EA);

    // 0. merged preproc (rounded weight packs) + split-K Wcomb
    preproc_kernel<<<576, 256>>>(Wq, Wk, Wv, bq, bk, bv, Wo, bo, Wke, bke, Weo, beo,
                                 W1, W2, Wqkv, bqkv, Wcat, Wfold, bcomb, W1t, W2t);
    GS<<<dim3(Dt / 64, 4, 4), 256, SMEM_GS>>>(Wfold, Wo + (size_t)Dt * Dt,
        Wcat + (size_t)Dt * Dt, 128, Dt, Dt, Dt,
        4, 0, 128, 0, (long long)128 * Dt, 0, 0,
        1.0f, nullptr, nullptr, 0, 2, 0, 0);

    // 1. LN(x), tf32-rounded
    ln512_kernel<<<BNr, 128>>>(x, ln_a_g, ln_a_b, nx, 1);

    // 2. fused qkv projection, outputs tf32-rounded
    dim3 gqkv(1536 / 128, BNr / 128, 1);
    GA<<<gqkv, 256, SMEM_GA>>>(nx, Wqkv, qkv, Dt, Dt, 1536, 1536,
        1, 0, 0, 0, 0, 0, 0, 1.0f, bqkv, nullptr, 0, 0, 0, 1);

    // 3. scores = alpha * Q @ K^T
    dim3 gsc(Nt / 128, Nt / 128, Bt * Ht);
    GT<<<gsc, 256, SMEM_GT>>>(qkv, qkv + 512, attn, DKt, 1536, 1536, Nt,
        Ht, (long long)Nt * 1536, 64, (long long)Nt * 1536, 64,
        (long long)Ht * NNt, (long long)NNt,
        0.08838834764831845f, nullptr, nullptr, 0, 0, 0, 0);

    // 4. fused edge LN + bias + softmax + ectx contraction
    edge_attn_kernel<<<BNr, 256, SMEM_EA>>>(attn, (const float4*)edge,
        ln_e_g, ln_e_b, Web, beb, mask, cat);

    // 5. ctx half of cat = attn @ V
    dim3 gcx(1, Nt / 128, Bt * Ht);
    GV<<<gcx, 256, SMEM_GV>>>(attn, qkv + 1024, cat, Nt, Nt, 1536, 768,
        Ht, (long long)Ht * NNt, (long long)NNt, (long long)Nt * 1536, 64,
        (long long)Nt * 768, 64,
        1.0f, nullptr, nullptr, 0, 0, 0, 0);

    // 6. x1 = x + cat @ Wcat + bcomb (cvt in-kernel; Wcomb half unrounded)
    dim3 gx1(Dt / 128, BNr / 128, 1);
    GAC<<<gx1, 256, SMEM_GAC>>>(cat, Wcat, x1, 768, 768, Dt, Dt,
        1, 0, 0, 0, 0, 0, 0, 1.0f, bcomb, x, Dt, 0, 0, 0);

    // 7. nx2 = LN(x1), tf32-rounded
    ln512_kernel<<<BNr, 128>>>(x1, ln_f_g, ln_f_b, nx2, 1);

    // 8. h1 = gelu(nx2 @ W1t + b1), tf32-rounded
    dim3 gf1(DFt / 128, BNr / 128, 1);
    GA<<<gf1, 256, SMEM_GA>>>(nx2, W1t, h1, Dt, Dt, DFt, DFt,
        1, 0, 0, 0, 0, 0, 0, 1.0f, b1, nullptr, 0, 0, 1, 1);

    // 9. out = x1 + h1 @ W2t + b2
    dim3 gf2(Dt / 128, BNr / 128, 1);
    GA<<<gf2, 256, SMEM_GA>>>(h1, W2t, out, DFt, DFt, Dt, Dt,
        1, 0, 0, 0, 0, 0, 0, 1.0f, b2, x1, Dt, 0, 0, 0);

    (void)in_sizes; (void)n_in; (void)out_size;
}

// round 16
// speedup vs baseline: 1.0272x; 1.0272x over previous
#include <cuda_runtime.h>
#include <cuda_bf16.h>
#include <math.h>
#include <stdint.h>

// ---------------- problem constants ----------------
#define Bt   8
#define Nt   384
#define Dt   512
#define Ht   8
#define DEt  32
#define DFt  2048
#define DKt  64
#define BNr  (Bt*Nt)            // 3072
#define NNt  (Nt*Nt)            // 147456

// scratch layout (floats)
#define OFF_NX     0LL
#define OFF_QKV    (OFF_NX    + (long long)BNr*Dt)
#define OFF_ATTN   (OFF_QKV   + (long long)BNr*3*Dt)
#define OFF_CAT    (OFF_ATTN  + (long long)Bt*Ht*NNt)   // [BNr][768] = [ctx | raw]
#define OFF_X1     (OFF_CAT   + (long long)BNr*768)
#define OFF_NX2    (OFF_X1    + (long long)BNr*Dt)
#define OFF_H1     (OFF_NX2   + (long long)BNr*Dt)
#define OFF_WQKV   (OFF_H1    + (long long)BNr*DFt)
#define OFF_BQKV   (OFF_WQKV  + (long long)Dt*3*Dt)
#define OFF_WFOLD  (OFF_BQKV  + 3*Dt)
#define OFF_WCAT   (OFF_WFOLD + (long long)Ht*DEt*Dt)   // [768][512]
#define OFF_BCOMB  (OFF_WCAT  + (long long)768*Dt)
#define OFF_W1T    (OFF_BCOMB + Dt)
#define OFF_W2T    (OFF_W1T   + (long long)Dt*DFt)
#define SCRATCH_TOTAL (OFF_W2T + (long long)DFt*Dt)

static __device__ float g_scratch[SCRATCH_TOTAL];

// ---------------- helpers ----------------
__device__ __forceinline__ float gelu_f(float v) {
    float t3 = v * v * v;
    return 0.5f * v * (1.0f + tanhf(0.7978845608028654f * (v + 0.044715f * t3)));
}

__device__ __forceinline__ float f2tf(float x) {
    uint32_t u;
    asm("cvt.rna.tf32.f32 %0, %1;" : "=r"(u) : "f"(x));
    return __uint_as_float(u);
}

__device__ __forceinline__ void mma_tf32(float* c, const uint32_t* a, const uint32_t* b) {
    asm volatile(
        "mma.sync.aligned.m16n8k8.row.col.f32.tf32.tf32.f32 "
        "{%0,%1,%2,%3}, {%4,%5,%6,%7}, {%8,%9}, {%0,%1,%2,%3};\n"
        : "+f"(c[0]), "+f"(c[1]), "+f"(c[2]), "+f"(c[3])
        : "r"(a[0]), "r"(a[1]), "r"(a[2]), "r"(a[3]), "r"(b[0]), "r"(b[1]));
}

__device__ __forceinline__ void cp_async16(float* smem_dst, const float* gmem_src) {
    uint32_t sa = (uint32_t)__cvta_generic_to_shared(smem_dst);
    asm volatile("cp.async.cg.shared.global [%0], [%1], 16;\n" :: "r"(sa), "l"(gmem_src));
}
__device__ __forceinline__ void cp_commit() {
    asm volatile("cp.async.commit_group;\n" ::: "memory");
}
template<int N>
__device__ __forceinline__ void cp_wait() {
    asm volatile("cp.async.wait_group %0;\n" :: "n"(N) : "memory");
}

__device__ __forceinline__ float blockReduce128(float v, bool isMax, float* sh) {
    #pragma unroll
    for (int o = 16; o; o >>= 1) {
        float o2 = __shfl_xor_sync(0xffffffffu, v, o);
        v = isMax ? fmaxf(v, o2) : v + o2;
    }
    __syncthreads();
    if ((threadIdx.x & 31) == 0) sh[threadIdx.x >> 5] = v;
    __syncthreads();
    float r = sh[0];
    #pragma unroll
    for (int k = 1; k < 4; k++) r = isMax ? fmaxf(r, sh[k]) : r + sh[k];
    return r;
}

// ---------------- LayerNorm over 512 cols (optionally tf32-rounded out) ----------------
__global__ __launch_bounds__(128) void ln512_kernel(
    const float* __restrict__ in, const float* __restrict__ g,
    const float* __restrict__ b, float* __restrict__ out, int round_out)
{
    __shared__ float sh[4];
    int row = blockIdx.x;
    int t = threadIdx.x;
    const float4* inr = (const float4*)(in + (size_t)row * Dt);
    float4 v = inr[t];
    float s  = v.x + v.y + v.z + v.w;
    float sq = v.x*v.x + v.y*v.y + v.z*v.z + v.w*v.w;
    float tot = blockReduce128(s, false, sh);
    __syncthreads();
    float totq = blockReduce128(sq, false, sh);
    float mean = tot * (1.0f / Dt);
    float var  = totq * (1.0f / Dt) - mean * mean;
    float inv  = rsqrtf(var + 1e-5f);
    float4 gg = ((const float4*)g)[t];
    float4 bb = ((const float4*)b)[t];
    float4 o;
    o.x = (v.x - mean) * inv * gg.x + bb.x;
    o.y = (v.y - mean) * inv * gg.y + bb.y;
    o.z = (v.z - mean) * inv * gg.z + bb.z;
    o.w = (v.w - mean) * inv * gg.w + bb.w;
    if (round_out) {
        o.x = f2tf(o.x); o.y = f2tf(o.y); o.z = f2tf(o.z); o.w = f2tf(o.w);
    }
    ((float4*)(out + (size_t)row * Dt))[t] = o;
}

// ---------------- merged preproc ----------------
__global__ __launch_bounds__(256) void preproc_kernel(
    const float* __restrict__ Wq, const float* __restrict__ Wk,
    const float* __restrict__ Wv,
    const float* __restrict__ bq, const float* __restrict__ bk,
    const float* __restrict__ bv,
    const float* __restrict__ Wo, const float* __restrict__ bo,
    const float* __restrict__ Wke, const float* __restrict__ bke,
    const float* __restrict__ Weo, const float* __restrict__ beo,
    const float* __restrict__ W1, const float* __restrict__ W2,
    float* __restrict__ Wqkv, float* __restrict__ bqkv,
    float* __restrict__ Wcat, float* __restrict__ Wfold,
    float* __restrict__ bcomb,
    float* __restrict__ W1t, float* __restrict__ W2t)
{
    int bx = blockIdx.x;
    int t = threadIdx.x;

    if (bx < 512) {
        int k = bx;
        for (int n = t; n < Dt; n += 256) {
            Wqkv[(size_t)k * 1536 + n]        = f2tf(Wq[(size_t)k * Dt + n]);
            Wqkv[(size_t)k * 1536 + 512 + n]  = f2tf(Wk[(size_t)k * Dt + n]);
            Wqkv[(size_t)k * 1536 + 1024 + n] = f2tf(Wv[(size_t)k * Dt + n]);
            Wcat[(size_t)k * Dt + n]          = f2tf(Wo[(size_t)k * Dt + n]);
        }
        for (int n = t; n < DFt; n += 256)
            W1t[(size_t)k * DFt + n] = f2tf(W1[(size_t)k * DFt + n]);
        #pragma unroll
        for (int r = 0; r < 4; r++) {
            int row = k * 4 + r;
            for (int n = t; n < Dt; n += 256)
                W2t[(size_t)row * Dt + n] = f2tf(W2[(size_t)row * Dt + n]);
        }
        if (k == 0) {
            for (int n = t; n < Dt; n += 256) {
                bqkv[n] = bq[n]; bqkv[512 + n] = bk[n]; bqkv[1024 + n] = bv[n];
            }
        }
    } else if (bx < 528) {
        __shared__ float sK[32 * 32];
        int idx = bx - 512;
        int h = idx >> 1;
        int d = (idx & 1) * 256 + t;
        for (int i = t; i < 1024; i += 256) sK[i] = Wke[i];
        __syncthreads();
        float wcol[32];
        #pragma unroll
        for (int c = 0; c < 32; c++)
            wcol[c] = Weo[(size_t)(h * 32 + c) * Dt + d];
        for (int k = 0; k < 32; k++) {
            float acc = 0.0f;
            #pragma unroll
            for (int c = 0; c < 32; c++) acc += sK[k * 32 + c] * wcol[c];
            Wfold[(size_t)(h * 32 + k) * Dt + d] = acc;
        }
    } else if (bx < 544) {
        __shared__ float sbf[Dt];
        __shared__ float red[8][33];
        int lane = t & 31, w = t >> 5;
        #pragma unroll
        for (int rr = 0; rr < 2; rr++) {
            int d = t + rr * 256;
            float acc = beo[d];
            for (int e = 0; e < Ht * DEt; e++)
                acc += bke[e & 31] * Weo[(size_t)e * Dt + d];
            sbf[d] = acc;
        }
        __syncthreads();
        int out = (bx - 528) * 32 + lane;
        float acc = 0.0f;
        for (int e = w; e < Dt; e += 8)
            acc += sbf[e] * Wo[(size_t)(Dt + e) * Dt + out];
        red[w][lane] = acc;
        __syncthreads();
        if (w == 0) {
            float s = bo[out];
            #pragma unroll
            for (int k = 0; k < 8; k++) s += red[k][lane];
            bcomb[out] = s;
        }
    } else {
        float4* dst = (float4*)(Wcat + (size_t)Dt * Dt);
        int base = (bx - 544) * 1024 + t;
        #pragma unroll
        for (int rr = 0; rr < 4; rr++)
            dst[base + rr * 256] = make_float4(0.f, 0.f, 0.f, 0.f);
    }
}

// ---------------- tf32 tensor-core GEMM ----------------
// 2-stage pipelines, 2 CTAs/SM (reg cap 128 via launch bounds).
// CVT=false: cp.async; CVT=true: LDG->reg->cvt->STS.
// accumulate: 0=store,1=read-add,2=atomicAdd. round_out: tf32-round epilogue.
template<int TBM, int TBN, int WM, int WN, bool TRANSB, bool CVT>
__global__ __launch_bounds__(256, 2) void gemm_tf32_kernel(
    const float* __restrict__ A, const float* __restrict__ Bm, float* __restrict__ C,
    int K, int lda, int ldb, int ldc,
    int batch2,
    long long sA1, long long sA2, long long sB1, long long sB2,
    long long sC1, long long sC2,
    float alpha, const float* __restrict__ bias,
    const float* __restrict__ addend, int ldadd,
    int accumulate, int act_gelu, int round_out)
{
    constexpr int BK = 32;
    constexpr int WNC = TBN / WN;
    constexpr int MF = WM / 16;
    constexpr int NF = WN / 8;
    constexpr int LDA_S = BK + 4;
    constexpr int LDB_S = TRANSB ? (BK + 4) : (TBN + 8);
    constexpr int BS_ROWS = TRANSB ? TBN : BK;
    constexpr int A_IT = TBM / 32;
    constexpr int B_IT = TRANSB ? (TBN / 32) : ((BK * TBN) / 1024);
    constexpr int A_STG = TBM * LDA_S;
    constexpr int B_STG = BS_ROWS * LDB_S;

    extern __shared__ float smem[];
    float* As = smem;
    float* Bs = smem + 2 * A_STG;

    int z = blockIdx.z;
    int z1 = z / batch2, z2 = z % batch2;
    A  += z1 * sA1 + z2 * sA2;
    Bm += z1 * sB1 + z2 * sB2;
    C  += z1 * sC1 + z2 * sC2;

    const int m_blk = blockIdx.y * TBM;
    const int n_blk = blockIdx.x * TBN;

    const int tid = threadIdx.x;
    const int warp = tid >> 5, lane = tid & 31;
    const int g = lane >> 2, tig = lane & 3;
    const int wm = warp / WNC, wn = warp % WNC;
    const int m0 = wm * WM, n0 = wn * WN;

    auto computeStage = [&](int s, float acc[MF][NF][4]) {
        #pragma unroll
        for (int ks = 0; ks < 4; ks++) {
            int kb = ks * 8;
            uint32_t afr[MF][4], bfr[NF][2];
            #pragma unroll
            for (int i = 0; i < MF; i++) {
                const float* ap = &As[(size_t)s * A_STG + (m0 + i * 16) * LDA_S + kb];
                afr[i][0] = __float_as_uint(ap[(size_t)g * LDA_S + tig]);
                afr[i][1] = __float_as_uint(ap[(size_t)(g + 8) * LDA_S + tig]);
                afr[i][2] = __float_as_uint(ap[(size_t)g * LDA_S + tig + 4]);
                afr[i][3] = __float_as_uint(ap[(size_t)(g + 8) * LDA_S + tig + 4]);
            }
            #pragma unroll
            for (int j = 0; j < NF; j++) {
                if (TRANSB) {
                    const float* bp = &Bs[(size_t)s * B_STG + (n0 + j * 8 + g) * LDB_S + kb];
                    bfr[j][0] = __float_as_uint(bp[tig]);
                    bfr[j][1] = __float_as_uint(bp[tig + 4]);
                } else {
                    const float* bp = &Bs[(size_t)s * B_STG + kb * LDB_S + n0 + j * 8 + g];
                    bfr[j][0] = __float_as_uint(bp[(size_t)tig * LDB_S]);
                    bfr[j][1] = __float_as_uint(bp[(size_t)(tig + 4) * LDB_S]);
                }
            }
            #pragma unroll
            for (int i = 0; i < MF; i++)
                #pragma unroll
                for (int j = 0; j < NF; j++)
                    mma_tf32(acc[i][j], afr[i], bfr[j]);
        }
    };

    float acc[MF][NF][4];
    #pragma unroll
    for (int i = 0; i < MF; i++)
        #pragma unroll
        for (int j = 0; j < NF; j++)
            #pragma unroll
            for (int q = 0; q < 4; q++) acc[i][j][q] = 0.0f;

    const int nk = K / BK;

    if constexpr (!CVT) {
        auto issueStage = [&](int s, int k0) {
            #pragma unroll
            for (int it = 0; it < A_IT; it++) {
                int idx = tid + it * 256;
                int r = idx >> 3, kq = (idx & 7) << 2;
                cp_async16(&As[(size_t)s * A_STG + r * LDA_S + kq],
                           &A[(size_t)(m_blk + r) * lda + k0 + kq]);
            }
            #pragma unroll
            for (int it = 0; it < B_IT; it++) {
                int idx = tid + it * 256;
                if (TRANSB) {
                    int r = idx >> 3, kq = (idx & 7) << 2;
                    cp_async16(&Bs[(size_t)s * B_STG + r * LDB_S + kq],
                               &Bm[(size_t)(n_blk + r) * ldb + k0 + kq]);
                } else {
                    int r = idx / (TBN / 4), c = (idx % (TBN / 4)) << 2;
                    cp_async16(&Bs[(size_t)s * B_STG + r * LDB_S + c],
                               &Bm[(size_t)(k0 + r) * ldb + n_blk + c]);
                }
            }
        };

        issueStage(0, 0); cp_commit();
        for (int kt = 0; kt < nk; kt++) {
            int s = kt & 1;
            if (kt + 1 < nk) {
                issueStage(s ^ 1, (kt + 1) * BK);
                cp_commit();
                cp_wait<1>();
            } else {
                cp_wait<0>();
            }
            __syncthreads();
            computeStage(s, acc);
            __syncthreads();
        }
    } else {
        float4 ra2[A_IT], rb2[B_IT];
        auto loadA2 = [&](int k0) {
            #pragma unroll
            for (int it = 0; it < A_IT; it++) {
                int idx = tid + it * 256;
                int r = idx >> 3, kq = (idx & 7) << 2;
                ra2[it] = *(const float4*)&A[(size_t)(m_blk + r) * lda + k0 + kq];
            }
        };
        auto storeA2 = [&](int s) {
            #pragma unroll
            for (int it = 0; it < A_IT; it++) {
                int idx = tid + it * 256;
                int r = idx >> 3, kq = (idx & 7) << 2;
                float4 v = ra2[it];
                v.x = f2tf(v.x); v.y = f2tf(v.y); v.z = f2tf(v.z); v.w = f2tf(v.w);
                *(float4*)&As[(size_t)s * A_STG + r * LDA_S + kq] = v;
            }
        };
        auto loadB2 = [&](int k0) {
            #pragma unroll
            for (int it = 0; it < B_IT; it++) {
                int idx = tid + it * 256;
                if (TRANSB) {
                    int r = idx >> 3, kq = (idx & 7) << 2;
                    rb2[it] = *(const float4*)&Bm[(size_t)(n_blk + r) * ldb + k0 + kq];
                } else {
                    int r = idx / (TBN / 4), c = (idx % (TBN / 4)) << 2;
                    rb2[it] = *(const float4*)&Bm[(size_t)(k0 + r) * ldb + n_blk + c];
                }
            }
        };
        auto storeB2 = [&](int s) {
            #pragma unroll
            for (int it = 0; it < B_IT; it++) {
                int idx = tid + it * 256;
                float4 v = rb2[it];
                v.x = f2tf(v.x); v.y = f2tf(v.y); v.z = f2tf(v.z); v.w = f2tf(v.w);
                if (TRANSB) {
                    int r = idx >> 3, kq = (idx & 7) << 2;
                    *(float4*)&Bs[(size_t)s * B_STG + r * LDB_S + kq] = v;
                } else {
                    int r = idx / (TBN / 4), c = (idx % (TBN / 4)) << 2;
                    *(float4*)&Bs[(size_t)s * B_STG + r * LDB_S + c] = v;
                }
            }
        };

        loadA2(0); loadB2(0);
        storeA2(0); storeB2(0);
        __syncthreads();

        for (int kt = 0; kt < nk; kt++) {
            int s = kt & 1;
            if (kt + 1 < nk) { loadA2((kt + 1) * BK); loadB2((kt + 1) * BK); }
            computeStage(s, acc);
            if (kt + 1 < nk) { storeA2(s ^ 1); storeB2(s ^ 1); }
            __syncthreads();
        }
    }

    #pragma unroll
    for (int i = 0; i < MF; i++) {
        int row0 = m_blk + m0 + i * 16 + g;
        #pragma unroll
        for (int half = 0; half < 2; half++) {
            int row = row0 + half * 8;
            size_t roff = (size_t)row * ldc;
            #pragma unroll
            for (int j = 0; j < NF; j++) {
                int col = n_blk + n0 + j * 8 + tig * 2;
                float v0 = acc[i][j][half * 2 + 0] * alpha;
                float v1 = acc[i][j][half * 2 + 1] * alpha;
                if (accumulate == 2) {
                    atomicAdd(&C[roff + col], v0);
                    atomicAdd(&C[roff + col + 1], v1);
                    continue;
                }
                if (bias)   { v0 += bias[col]; v1 += bias[col + 1]; }
                if (addend) {
                    const float* ad = &addend[(size_t)row * ldadd + col];
                    v0 += ad[0]; v1 += ad[1];
                }
                if (accumulate == 1) { v0 += C[roff + col]; v1 += C[roff + col + 1]; }
                if (act_gelu)   { v0 = gelu_f(v0); v1 = gelu_f(v1); }
                if (round_out)  { v0 = f2tf(v0); v1 = f2tf(v1); }
                float2 o = make_float2(v0, v1);
                *(float2*)&C[roff + col] = o;
            }
        }
    }
}

// ---------------- fused edge: LN + bias + softmax + ectx contraction ----------------
__global__ __launch_bounds__(256) void edge_attn_kernel(
    float* __restrict__ attn, const float4* __restrict__ edge4,
    const float* __restrict__ eg, const float* __restrict__ eb,
    const float* __restrict__ Web, const float* __restrict__ beb,
    const unsigned char* __restrict__ mask, float* __restrict__ cat)
{
    constexpr int LDAS = 388;
    constexpr int LDBS = 40;
    extern __shared__ float smem[];
    float* sA = smem;
    float* sB = smem + 16 * LDAS;
    float* sbias = sB + Nt * LDBS;

    int bi = blockIdx.x;
    int b = bi / Nt, i = bi % Nt;
    int t = threadIdx.x;
    int l8 = t & 7, rgrp = t >> 3;

    float4 g4 = __ldg(&((const float4*)eg)[l8]);
    float4 b4 = __ldg(&((const float4*)eb)[l8]);
    float4 wb = __ldg(&((const float4*)Web)[l8]);
    float bb = __ldg(beb);

    #pragma unroll
    for (int pp = 0; pp < 12; pp++) {
        int j = pp * 32 + rgrp;
        float4 e = edge4[((long long)bi * Nt + j) * 8 + l8];
        float s = e.x + e.y + e.z + e.w;
        s += __shfl_xor_sync(0xffffffffu, s, 4);
        s += __shfl_xor_sync(0xffffffffu, s, 2);
        s += __shfl_xor_sync(0xffffffffu, s, 1);
        float mean = s * (1.0f / 32.0f);
        float4 d = make_float4(e.x - mean, e.y - mean, e.z - mean, e.w - mean);
        float vq = d.x*d.x + d.y*d.y + d.z*d.z + d.w*d.w;
        vq += __shfl_xor_sync(0xffffffffu, vq, 4);
        vq += __shfl_xor_sync(0xffffffffu, vq, 2);
        vq += __shfl_xor_sync(0xffffffffu, vq, 1);
        float inv = rsqrtf(vq * (1.0f / 32.0f) + 1e-5f);
        float4 ne;
        ne.x = d.x * inv * g4.x + b4.x;
        ne.y = d.y * inv * g4.y + b4.y;
        ne.z = d.z * inv * g4.z + b4.z;
        ne.w = d.w * inv * g4.w + b4.w;
        float pb = ne.x*wb.x + ne.y*wb.y + ne.z*wb.z + ne.w*wb.w;
        pb += __shfl_xor_sync(0xffffffffu, pb, 4);
        pb += __shfl_xor_sync(0xffffffffu, pb, 2);
        pb += __shfl_xor_sync(0xffffffffu, pb, 1);
        if (l8 == 0) sbias[j] = (pb + bb) * 0.70710678118654752f;
        ne.x = f2tf(ne.x); ne.y = f2tf(ne.y);
        ne.z = f2tf(ne.z); ne.w = f2tf(ne.w);
        *(float4*)&sB[j * LDBS + l8 * 4] = ne;
    }
    __syncthreads();

    int warp = t >> 5, lane = t & 31;
    float* sp = attn + (((size_t)(b * Ht + warp)) * Nt + i) * Nt;
    const unsigned char* mp = mask + (size_t)bi * Nt;
    float v[12];
    float mx = -INFINITY;
    #pragma unroll
    for (int r = 0; r < 12; r++) {
        int j = lane + r * 32;
        float s = sp[j] + sbias[j];
        if (mp[j]) s = -INFINITY;
        v[r] = s;
        mx = fmaxf(mx, s);
    }
    #pragma unroll
    for (int o = 16; o; o >>= 1) mx = fmaxf(mx, __shfl_xor_sync(0xffffffffu, mx, o));
    float sum = 0.0f;
    #pragma unroll
    for (int r = 0; r < 12; r++) { v[r] = __expf(v[r] - mx); sum += v[r]; }
    #pragma unroll
    for (int o = 16; o; o >>= 1) sum += __shfl_xor_sync(0xffffffffu, sum, o);
    float invs = 1.0f / sum;
    #pragma unroll
    for (int r = 0; r < 12; r++) {
        int j = lane + r * 32;
        float val = f2tf(v[r] * invs);
        sp[j] = val;
        sA[warp * LDAS + j] = val;
    }
    __syncthreads();

    if (warp < 4) {
        int g = lane >> 2, tig = lane & 3;
        int n0 = warp * 8;
        float acc[4] = {0.0f, 0.0f, 0.0f, 0.0f};
        #pragma unroll
        for (int k8 = 0; k8 < 48; k8++) {
            int kb = k8 * 8;
            uint32_t afr[4], bfr[2];
            afr[0] = __float_as_uint(sA[g * LDAS + kb + tig]);
            afr[1] = __float_as_uint(sA[(g + 8) * LDAS + kb + tig]);
            afr[2] = __float_as_uint(sA[g * LDAS + kb + tig + 4]);
            afr[3] = __float_as_uint(sA[(g + 8) * LDAS + kb + tig + 4]);
            bfr[0] = __float_as_uint(sB[(kb + tig) * LDBS + n0 + g]);
            bfr[1] = __float_as_uint(sB[(kb + tig + 4) * LDBS + n0 + g]);
            mma_tf32(acc, afr, bfr);
        }
        float2 o = make_float2(acc[0], acc[1]);
        *(float2*)&cat[(size_t)bi * 768 + 512 + g * DEt + n0 + tig * 2] = o;
    }
}

// ---------------- launch ----------------
extern "C" void kernel_launch(void* const* d_in, const int* in_sizes, int n_in,
                              void* d_out, int out_size)
{
    const float* x      = (const float*)d_in[0];
    const float* edge   = (const float*)d_in[1];
    const unsigned char* mask = (const unsigned char*)d_in[2];
    const float* ln_a_g = (const float*)d_in[3];
    const float* ln_a_b = (const float*)d_in[4];
    const float* ln_e_g = (const float*)d_in[5];
    const float* ln_e_b = (const float*)d_in[6];
    const float* Wq = (const float*)d_in[7];   const float* bq = (const float*)d_in[8];
    const float* Wk = (const float*)d_in[9];   const float* bk = (const float*)d_in[10];
    const float* Wv = (const float*)d_in[11];  const float* bv = (const float*)d_in[12];
    const float* Wke = (const float*)d_in[13]; const float* bke = (const float*)d_in[14];
    const float* Web = (const float*)d_in[15]; const float* beb = (const float*)d_in[16];
    const float* Weo = (const float*)d_in[17]; const float* beo = (const float*)d_in[18];
    const float* Wo  = (const float*)d_in[19]; const float* bo  = (const float*)d_in[20];
    const float* ln_f_g = (const float*)d_in[21];
    const float* ln_f_b = (const float*)d_in[22];
    const float* W1 = (const float*)d_in[23];  const float* b1 = (const float*)d_in[24];
    const float* W2 = (const float*)d_in[25];  const float* b2 = (const float*)d_in[26];
    float* out = (float*)d_out;

    float* base;
    cudaGetSymbolAddress((void**)&base, g_scratch);
    float* nx    = base + OFF_NX;
    float* qkv   = base + OFF_QKV;
    float* attn  = base + OFF_ATTN;
    float* cat   = base + OFF_CAT;
    float* x1    = base + OFF_X1;
    float* nx2   = base + OFF_NX2;
    float* h1    = base + OFF_H1;
    float* Wqkv  = base + OFF_WQKV;
    float* bqkv  = base + OFF_BQKV;
    float* Wfold = base + OFF_WFOLD;
    float* Wcat  = base + OFF_WCAT;
    float* bcomb = base + OFF_BCOMB;
    float* W1t   = base + OFF_W1T;
    float* W2t   = base + OFF_W2T;

    auto GA  = gemm_tf32_kernel<128, 128, 64, 32, false, false>;
    auto GAC = gemm_tf32_kernel<128, 128, 64, 32, false, true>;
    auto GT  = gemm_tf32_kernel<128, 128, 64, 32, true,  false>;
    auto GV  = gemm_tf32_kernel<128, 64, 32, 32, false, false>;
    auto GS  = gemm_tf32_kernel<64, 64, 16, 32, false, true>;

    constexpr int SMEM_GA = 2 * (128 * 36 + 32 * 136) * 4;    // 71680
    constexpr int SMEM_GT = 2 * (128 * 36 + 128 * 36) * 4;    // 73728
    constexpr int SMEM_GV = 2 * (128 * 36 + 32 * 72) * 4;     // 55296
    constexpr int SMEM_GS = 2 * (64 * 36 + 32 * 72) * 4;      // 36864
    constexpr int SMEM_EA = (16 * 388 + 384 * 40 + 384) * 4;  // 87808
    cudaFuncSetAttribute(GA,  cudaFuncAttributeMaxDynamicSharedMemorySize, SMEM_GA);
    cudaFuncSetAttribute(GAC, cudaFuncAttributeMaxDynamicSharedMemorySize, SMEM_GA);
    cudaFuncSetAttribute(GT,  cudaFuncAttributeMaxDynamicSharedMemorySize, SMEM_GT);
    cudaFuncSetAttribute(GV,  cudaFuncAttributeMaxDynamicSharedMemorySize, SMEM_GV);
    cudaFuncSetAttribute(GS,  cudaFuncAttributeMaxDynamicSharedMemorySize, SMEM_GS);
    cudaFuncSetAttribute(edge_attn_kernel, cudaFuncAttributeMaxDynamicSharedMemorySize, SMEM_EA);

    // 0. merged preproc (rounded weight packs) + split-K Wcomb
    preproc_kernel<<<576, 256>>>(Wq, Wk, Wv, bq, bk, bv, Wo, bo, Wke, bke, Weo, beo,
                                 W1, W2, Wqkv, bqkv, Wcat, Wfold, bcomb, W1t, W2t);
    GS<<<dim3(Dt / 64, 4, 4), 256, SMEM_GS>>>(Wfold, Wo + (size_t)Dt * Dt,
        Wcat + (size_t)Dt * Dt, 128, Dt, Dt, Dt,
        4, 0, 128, 0, (long long)128 * Dt, 0, 0,
        1.0f, nullptr, nullptr, 0, 2, 0, 0);

    // 1. LN(x), tf32-rounded
    ln512_kernel<<<BNr, 128>>>(x, ln_a_g, ln_a_b, nx, 1);

    // 2. fused qkv projection, outputs tf32-rounded
    dim3 gqkv(1536 / 128, BNr / 128, 1);
    GA<<<gqkv, 256, SMEM_GA>>>(nx, Wqkv, qkv, Dt, Dt, 1536, 1536,
        1, 0, 0, 0, 0, 0, 0, 1.0f, bqkv, nullptr, 0, 0, 0, 1);

    // 3. scores = alpha * Q @ K^T
    dim3 gsc(Nt / 128, Nt / 128, Bt * Ht);
    GT<<<gsc, 256, SMEM_GT>>>(qkv, qkv + 512, attn, DKt, 1536, 1536, Nt,
        Ht, (long long)Nt * 1536, 64, (long long)Nt * 1536, 64,
        (long long)Ht * NNt, (long long)NNt,
        0.08838834764831845f, nullptr, nullptr, 0, 0, 0, 0);

    // 4. fused edge LN + bias + softmax + ectx contraction
    edge_attn_kernel<<<BNr, 256, SMEM_EA>>>(attn, (const float4*)edge,
        ln_e_g, ln_e_b, Web, beb, mask, cat);

    // 5. ctx half of cat = attn @ V
    dim3 gcx(1, Nt / 128, Bt * Ht);
    GV<<<gcx, 256, SMEM_GV>>>(attn, qkv + 1024, cat, Nt, Nt, 1536, 768,
        Ht, (long long)Ht * NNt, (long long)NNt, (long long)Nt * 1536, 64,
        (long long)Nt * 768, 64,
        1.0f, nullptr, nullptr, 0, 0, 0, 0);

    // 6. x1 = x + cat @ Wcat + bcomb (cvt in-kernel; Wcomb half unrounded)
    dim3 gx1(Dt / 128, BNr / 128, 1);
    GAC<<<gx1, 256, SMEM_GA>>>(cat, Wcat, x1, 768, 768, Dt, Dt,
        1, 0, 0, 0, 0, 0, 0, 1.0f, bcomb, x, Dt, 0, 0, 0);

    // 7. nx2 = LN(x1), tf32-rounded
    ln512_kernel<<<BNr, 128>>>(x1, ln_f_g, ln_f_b, nx2, 1);

    // 8. h1 = gelu(nx2 @ W1t + b1), tf32-rounded
    dim3 gf1(DFt / 128, BNr / 128, 1);
    GA<<<gf1, 256, SMEM_GA>>>(nx2, W1t, h1, Dt, Dt, DFt, DFt,
        1, 0, 0, 0, 0, 0, 0, 1.0f, b1, nullptr, 0, 0, 1, 1);

    // 9. out = x1 + h1 @ W2t + b2
    dim3 gf2(Dt / 128, BNr / 128, 1);
    GA<<<gf2, 256, SMEM_GA>>>(h1, W2t, out, DFt, DFt, Dt, Dt,
        1, 0, 0, 0, 0, 0, 0, 1.0f, b2, x1, Dt, 0, 0, 0);

    (void)in_sizes; (void)n_in; (void)out_size;
}

// round 17
// speedup vs baseline: 1.0598x; 1.0317x over previous
#include <cuda_runtime.h>
#include <cuda_bf16.h>
#include <math.h>
#include <stdint.h>

// ---------------- problem constants ----------------
#define Bt   8
#define Nt   384
#define Dt   512
#define Ht   8
#define DEt  32
#define DFt  2048
#define DKt  64
#define BNr  (Bt*Nt)            // 3072
#define NNt  (Nt*Nt)            // 147456

// scratch layout (floats)
#define OFF_NX     0LL
#define OFF_QKV    (OFF_NX    + (long long)BNr*Dt)
#define OFF_ATTN   (OFF_QKV   + (long long)BNr*3*Dt)
#define OFF_CAT    (OFF_ATTN  + (long long)Bt*Ht*NNt)   // [BNr][768] = [ctx | raw]
#define OFF_X1     (OFF_CAT   + (long long)BNr*768)
#define OFF_NX2    (OFF_X1    + (long long)BNr*Dt)
#define OFF_H1     (OFF_NX2   + (long long)BNr*Dt)
#define OFF_WQKV   (OFF_H1    + (long long)BNr*DFt)
#define OFF_BQKV   (OFF_WQKV  + (long long)Dt*3*Dt)
#define OFF_WFOLD  (OFF_BQKV  + 3*Dt)
#define OFF_WCAT   (OFF_WFOLD + (long long)Ht*DEt*Dt)   // [768][512]
#define OFF_BCOMB  (OFF_WCAT  + (long long)768*Dt)
#define OFF_W1T    (OFF_BCOMB + Dt)
#define OFF_W2T    (OFF_W1T   + (long long)Dt*DFt)
#define SCRATCH_TOTAL (OFF_W2T + (long long)DFt*Dt)

static __device__ float g_scratch[SCRATCH_TOTAL];

// ---------------- helpers ----------------
__device__ __forceinline__ float gelu_f(float v) {
    float t3 = v * v * v;
    return 0.5f * v * (1.0f + tanhf(0.7978845608028654f * (v + 0.044715f * t3)));
}

__device__ __forceinline__ float f2tf(float x) {
    uint32_t u;
    asm("cvt.rna.tf32.f32 %0, %1;" : "=r"(u) : "f"(x));
    return __uint_as_float(u);
}

__device__ __forceinline__ void mma_tf32(float* c, const uint32_t* a, const uint32_t* b) {
    asm volatile(
        "mma.sync.aligned.m16n8k8.row.col.f32.tf32.tf32.f32 "
        "{%0,%1,%2,%3}, {%4,%5,%6,%7}, {%8,%9}, {%0,%1,%2,%3};\n"
        : "+f"(c[0]), "+f"(c[1]), "+f"(c[2]), "+f"(c[3])
        : "r"(a[0]), "r"(a[1]), "r"(a[2]), "r"(a[3]), "r"(b[0]), "r"(b[1]));
}

__device__ __forceinline__ void cp_async16(float* smem_dst, const float* gmem_src) {
    uint32_t sa = (uint32_t)__cvta_generic_to_shared(smem_dst);
    asm volatile("cp.async.cg.shared.global [%0], [%1], 16;\n" :: "r"(sa), "l"(gmem_src));
}
__device__ __forceinline__ void cp_commit() {
    asm volatile("cp.async.commit_group;\n" ::: "memory");
}
template<int N>
__device__ __forceinline__ void cp_wait() {
    asm volatile("cp.async.wait_group %0;\n" :: "n"(N) : "memory");
}

__device__ __forceinline__ float blockReduce128(float v, bool isMax, float* sh) {
    #pragma unroll
    for (int o = 16; o; o >>= 1) {
        float o2 = __shfl_xor_sync(0xffffffffu, v, o);
        v = isMax ? fmaxf(v, o2) : v + o2;
    }
    __syncthreads();
    if ((threadIdx.x & 31) == 0) sh[threadIdx.x >> 5] = v;
    __syncthreads();
    float r = sh[0];
    #pragma unroll
    for (int k = 1; k < 4; k++) r = isMax ? fmaxf(r, sh[k]) : r + sh[k];
    return r;
}

// ---------------- LayerNorm over 512 cols (optionally tf32-rounded out) ----------------
__global__ __launch_bounds__(128) void ln512_kernel(
    const float* __restrict__ in, const float* __restrict__ g,
    const float* __restrict__ b, float* __restrict__ out, int round_out)
{
    __shared__ float sh[4];
    int row = blockIdx.x;
    int t = threadIdx.x;
    const float4* inr = (const float4*)(in + (size_t)row * Dt);
    float4 v = inr[t];
    float s  = v.x + v.y + v.z + v.w;
    float sq = v.x*v.x + v.y*v.y + v.z*v.z + v.w*v.w;
    float tot = blockReduce128(s, false, sh);
    __syncthreads();
    float totq = blockReduce128(sq, false, sh);
    float mean = tot * (1.0f / Dt);
    float var  = totq * (1.0f / Dt) - mean * mean;
    float inv  = rsqrtf(var + 1e-5f);
    float4 gg = ((const float4*)g)[t];
    float4 bb = ((const float4*)b)[t];
    float4 o;
    o.x = (v.x - mean) * inv * gg.x + bb.x;
    o.y = (v.y - mean) * inv * gg.y + bb.y;
    o.z = (v.z - mean) * inv * gg.z + bb.z;
    o.w = (v.w - mean) * inv * gg.w + bb.w;
    if (round_out) {
        o.x = f2tf(o.x); o.y = f2tf(o.y); o.z = f2tf(o.z); o.w = f2tf(o.w);
    }
    ((float4*)(out + (size_t)row * Dt))[t] = o;
}

// ---------------- round a buffer to tf32 in place ----------------
__global__ __launch_bounds__(256) void round_tf_kernel(float4* __restrict__ p)
{
    int idx = blockIdx.x * 256 + threadIdx.x;
    float4 v = p[idx];
    v.x = f2tf(v.x); v.y = f2tf(v.y); v.z = f2tf(v.z); v.w = f2tf(v.w);
    p[idx] = v;
}

// ---------------- merged preproc ----------------
__global__ __launch_bounds__(256) void preproc_kernel(
    const float* __restrict__ Wq, const float* __restrict__ Wk,
    const float* __restrict__ Wv,
    const float* __restrict__ bq, const float* __restrict__ bk,
    const float* __restrict__ bv,
    const float* __restrict__ Wo, const float* __restrict__ bo,
    const float* __restrict__ Wke, const float* __restrict__ bke,
    const float* __restrict__ Weo, const float* __restrict__ beo,
    const float* __restrict__ W1, const float* __restrict__ W2,
    float* __restrict__ Wqkv, float* __restrict__ bqkv,
    float* __restrict__ Wcat, float* __restrict__ Wfold,
    float* __restrict__ bcomb,
    float* __restrict__ W1t, float* __restrict__ W2t)
{
    int bx = blockIdx.x;
    int t = threadIdx.x;

    if (bx < 512) {
        int k = bx;
        for (int n = t; n < Dt; n += 256) {
            Wqkv[(size_t)k * 1536 + n]        = f2tf(Wq[(size_t)k * Dt + n]);
            Wqkv[(size_t)k * 1536 + 512 + n]  = f2tf(Wk[(size_t)k * Dt + n]);
            Wqkv[(size_t)k * 1536 + 1024 + n] = f2tf(Wv[(size_t)k * Dt + n]);
            Wcat[(size_t)k * Dt + n]          = f2tf(Wo[(size_t)k * Dt + n]);
        }
        for (int n = t; n < DFt; n += 256)
            W1t[(size_t)k * DFt + n] = f2tf(W1[(size_t)k * DFt + n]);
        #pragma unroll
        for (int r = 0; r < 4; r++) {
            int row = k * 4 + r;
            for (int n = t; n < Dt; n += 256)
                W2t[(size_t)row * Dt + n] = f2tf(W2[(size_t)row * Dt + n]);
        }
        if (k == 0) {
            for (int n = t; n < Dt; n += 256) {
                bqkv[n] = bq[n]; bqkv[512 + n] = bk[n]; bqkv[1024 + n] = bv[n];
            }
        }
    } else if (bx < 528) {
        __shared__ float sK[32 * 32];
        int idx = bx - 512;
        int h = idx >> 1;
        int d = (idx & 1) * 256 + t;
        for (int i = t; i < 1024; i += 256) sK[i] = Wke[i];
        __syncthreads();
        float wcol[32];
        #pragma unroll
        for (int c = 0; c < 32; c++)
            wcol[c] = Weo[(size_t)(h * 32 + c) * Dt + d];
        for (int k = 0; k < 32; k++) {
            float acc = 0.0f;
            #pragma unroll
            for (int c = 0; c < 32; c++) acc += sK[k * 32 + c] * wcol[c];
            Wfold[(size_t)(h * 32 + k) * Dt + d] = acc;
        }
    } else if (bx < 544) {
        __shared__ float sbf[Dt];
        __shared__ float red[8][33];
        int lane = t & 31, w = t >> 5;
        #pragma unroll
        for (int rr = 0; rr < 2; rr++) {
            int d = t + rr * 256;
            float acc = beo[d];
            for (int e = 0; e < Ht * DEt; e++)
                acc += bke[e & 31] * Weo[(size_t)e * Dt + d];
            sbf[d] = acc;
        }
        __syncthreads();
        int out = (bx - 528) * 32 + lane;
        float acc = 0.0f;
        for (int e = w; e < Dt; e += 8)
            acc += sbf[e] * Wo[(size_t)(Dt + e) * Dt + out];
        red[w][lane] = acc;
        __syncthreads();
        if (w == 0) {
            float s = bo[out];
            #pragma unroll
            for (int k = 0; k < 8; k++) s += red[k][lane];
            bcomb[out] = s;
        }
    } else {
        float4* dst = (float4*)(Wcat + (size_t)Dt * Dt);
        int base = (bx - 544) * 1024 + t;
        #pragma unroll
        for (int rr = 0; rr < 4; rr++)
            dst[base + rr * 256] = make_float4(0.f, 0.f, 0.f, 0.f);
    }
}

// ---------------- tf32 tensor-core GEMM ----------------
// 2-stage pipelines, 2 CTAs/SM (reg cap 128 via launch bounds).
// CVT=false: cp.async; CVT=true: LDG->reg->cvt->STS.
// accumulate: 0=store,1=read-add,2=atomicAdd. round_out: tf32-round epilogue.
template<int TBM, int TBN, int WM, int WN, bool TRANSB, bool CVT>
__global__ __launch_bounds__(256, 2) void gemm_tf32_kernel(
    const float* __restrict__ A, const float* __restrict__ Bm, float* __restrict__ C,
    int K, int lda, int ldb, int ldc,
    int batch2,
    long long sA1, long long sA2, long long sB1, long long sB2,
    long long sC1, long long sC2,
    float alpha, const float* __restrict__ bias,
    const float* __restrict__ addend, int ldadd,
    int accumulate, int act_gelu, int round_out)
{
    constexpr int BK = 32;
    constexpr int WNC = TBN / WN;
    constexpr int MF = WM / 16;
    constexpr int NF = WN / 8;
    constexpr int LDA_S = BK + 4;
    constexpr int LDB_S = TRANSB ? (BK + 4) : (TBN + 8);
    constexpr int BS_ROWS = TRANSB ? TBN : BK;
    constexpr int A_IT = TBM / 32;
    constexpr int B_IT = TRANSB ? (TBN / 32) : ((BK * TBN) / 1024);
    constexpr int A_STG = TBM * LDA_S;
    constexpr int B_STG = BS_ROWS * LDB_S;

    extern __shared__ float smem[];
    float* As = smem;
    float* Bs = smem + 2 * A_STG;

    int z = blockIdx.z;
    int z1 = z / batch2, z2 = z % batch2;
    A  += z1 * sA1 + z2 * sA2;
    Bm += z1 * sB1 + z2 * sB2;
    C  += z1 * sC1 + z2 * sC2;

    const int m_blk = blockIdx.y * TBM;
    const int n_blk = blockIdx.x * TBN;

    const int tid = threadIdx.x;
    const int warp = tid >> 5, lane = tid & 31;
    const int g = lane >> 2, tig = lane & 3;
    const int wm = warp / WNC, wn = warp % WNC;
    const int m0 = wm * WM, n0 = wn * WN;

    auto computeStage = [&](int s, float acc[MF][NF][4]) {
        #pragma unroll
        for (int ks = 0; ks < 4; ks++) {
            int kb = ks * 8;
            uint32_t afr[MF][4], bfr[NF][2];
            #pragma unroll
            for (int i = 0; i < MF; i++) {
                const float* ap = &As[(size_t)s * A_STG + (m0 + i * 16) * LDA_S + kb];
                afr[i][0] = __float_as_uint(ap[(size_t)g * LDA_S + tig]);
                afr[i][1] = __float_as_uint(ap[(size_t)(g + 8) * LDA_S + tig]);
                afr[i][2] = __float_as_uint(ap[(size_t)g * LDA_S + tig + 4]);
                afr[i][3] = __float_as_uint(ap[(size_t)(g + 8) * LDA_S + tig + 4]);
            }
            #pragma unroll
            for (int j = 0; j < NF; j++) {
                if (TRANSB) {
                    const float* bp = &Bs[(size_t)s * B_STG + (n0 + j * 8 + g) * LDB_S + kb];
                    bfr[j][0] = __float_as_uint(bp[tig]);
                    bfr[j][1] = __float_as_uint(bp[tig + 4]);
                } else {
                    const float* bp = &Bs[(size_t)s * B_STG + kb * LDB_S + n0 + j * 8 + g];
                    bfr[j][0] = __float_as_uint(bp[(size_t)tig * LDB_S]);
                    bfr[j][1] = __float_as_uint(bp[(size_t)(tig + 4) * LDB_S]);
                }
            }
            #pragma unroll
            for (int i = 0; i < MF; i++)
                #pragma unroll
                for (int j = 0; j < NF; j++)
                    mma_tf32(acc[i][j], afr[i], bfr[j]);
        }
    };

    float acc[MF][NF][4];
    #pragma unroll
    for (int i = 0; i < MF; i++)
        #pragma unroll
        for (int j = 0; j < NF; j++)
            #pragma unroll
            for (int q = 0; q < 4; q++) acc[i][j][q] = 0.0f;

    const int nk = K / BK;

    if constexpr (!CVT) {
        auto issueStage = [&](int s, int k0) {
            #pragma unroll
            for (int it = 0; it < A_IT; it++) {
                int idx = tid + it * 256;
                int r = idx >> 3, kq = (idx & 7) << 2;
                cp_async16(&As[(size_t)s * A_STG + r * LDA_S + kq],
                           &A[(size_t)(m_blk + r) * lda + k0 + kq]);
            }
            #pragma unroll
            for (int it = 0; it < B_IT; it++) {
                int idx = tid + it * 256;
                if (TRANSB) {
                    int r = idx >> 3, kq = (idx & 7) << 2;
                    cp_async16(&Bs[(size_t)s * B_STG + r * LDB_S + kq],
                               &Bm[(size_t)(n_blk + r) * ldb + k0 + kq]);
                } else {
                    int r = idx / (TBN / 4), c = (idx % (TBN / 4)) << 2;
                    cp_async16(&Bs[(size_t)s * B_STG + r * LDB_S + c],
                               &Bm[(size_t)(k0 + r) * ldb + n_blk + c]);
                }
            }
        };

        issueStage(0, 0); cp_commit();
        for (int kt = 0; kt < nk; kt++) {
            int s = kt & 1;
            if (kt + 1 < nk) {
                issueStage(s ^ 1, (kt + 1) * BK);
                cp_commit();
                cp_wait<1>();
            } else {
                cp_wait<0>();
            }
            __syncthreads();
            computeStage(s, acc);
            __syncthreads();
        }
    } else {
        float4 ra2[A_IT], rb2[B_IT];
        auto loadA2 = [&](int k0) {
            #pragma unroll
            for (int it = 0; it < A_IT; it++) {
                int idx = tid + it * 256;
                int r = idx >> 3, kq = (idx & 7) << 2;
                ra2[it] = *(const float4*)&A[(size_t)(m_blk + r) * lda + k0 + kq];
            }
        };
        auto storeA2 = [&](int s) {
            #pragma unroll
            for (int it = 0; it < A_IT; it++) {
                int idx = tid + it * 256;
                int r = idx >> 3, kq = (idx & 7) << 2;
                float4 v = ra2[it];
                v.x = f2tf(v.x); v.y = f2tf(v.y); v.z = f2tf(v.z); v.w = f2tf(v.w);
                *(float4*)&As[(size_t)s * A_STG + r * LDA_S + kq] = v;
            }
        };
        auto loadB2 = [&](int k0) {
            #pragma unroll
            for (int it = 0; it < B_IT; it++) {
                int idx = tid + it * 256;
                if (TRANSB) {
                    int r = idx >> 3, kq = (idx & 7) << 2;
                    rb2[it] = *(const float4*)&Bm[(size_t)(n_blk + r) * ldb + k0 + kq];
                } else {
                    int r = idx / (TBN / 4), c = (idx % (TBN / 4)) << 2;
                    rb2[it] = *(const float4*)&Bm[(size_t)(k0 + r) * ldb + n_blk + c];
                }
            }
        };
        auto storeB2 = [&](int s) {
            #pragma unroll
            for (int it = 0; it < B_IT; it++) {
                int idx = tid + it * 256;
                float4 v = rb2[it];
                v.x = f2tf(v.x); v.y = f2tf(v.y); v.z = f2tf(v.z); v.w = f2tf(v.w);
                if (TRANSB) {
                    int r = idx >> 3, kq = (idx & 7) << 2;
                    *(float4*)&Bs[(size_t)s * B_STG + r * LDB_S + kq] = v;
                } else {
                    int r = idx / (TBN / 4), c = (idx % (TBN / 4)) << 2;
                    *(float4*)&Bs[(size_t)s * B_STG + r * LDB_S + c] = v;
                }
            }
        };

        loadA2(0); loadB2(0);
        storeA2(0); storeB2(0);
        __syncthreads();

        for (int kt = 0; kt < nk; kt++) {
            int s = kt & 1;
            if (kt + 1 < nk) { loadA2((kt + 1) * BK); loadB2((kt + 1) * BK); }
            computeStage(s, acc);
            if (kt + 1 < nk) { storeA2(s ^ 1); storeB2(s ^ 1); }
            __syncthreads();
        }
    }

    #pragma unroll
    for (int i = 0; i < MF; i++) {
        int row0 = m_blk + m0 + i * 16 + g;
        #pragma unroll
        for (int half = 0; half < 2; half++) {
            int row = row0 + half * 8;
            size_t roff = (size_t)row * ldc;
            #pragma unroll
            for (int j = 0; j < NF; j++) {
                int col = n_blk + n0 + j * 8 + tig * 2;
                float v0 = acc[i][j][half * 2 + 0] * alpha;
                float v1 = acc[i][j][half * 2 + 1] * alpha;
                if (accumulate == 2) {
                    atomicAdd(&C[roff + col], v0);
                    atomicAdd(&C[roff + col + 1], v1);
                    continue;
                }
                if (bias)   { v0 += bias[col]; v1 += bias[col + 1]; }
                if (addend) {
                    const float* ad = &addend[(size_t)row * ldadd + col];
                    v0 += ad[0]; v1 += ad[1];
                }
                if (accumulate == 1) { v0 += C[roff + col]; v1 += C[roff + col + 1]; }
                if (act_gelu)   { v0 = gelu_f(v0); v1 = gelu_f(v1); }
                if (round_out)  { v0 = f2tf(v0); v1 = f2tf(v1); }
                float2 o = make_float2(v0, v1);
                *(float2*)&C[roff + col] = o;
            }
        }
    }
}

// ---------------- fused edge: LN + bias + softmax + ectx contraction ----------------
__global__ __launch_bounds__(256) void edge_attn_kernel(
    float* __restrict__ attn, const float4* __restrict__ edge4,
    const float* __restrict__ eg, const float* __restrict__ eb,
    const float* __restrict__ Web, const float* __restrict__ beb,
    const unsigned char* __restrict__ mask, float* __restrict__ cat)
{
    constexpr int LDAS = 388;
    constexpr int LDBS = 40;
    extern __shared__ float smem[];
    float* sA = smem;
    float* sB = smem + 16 * LDAS;
    float* sbias = sB + Nt * LDBS;

    int bi = blockIdx.x;
    int b = bi / Nt, i = bi % Nt;
    int t = threadIdx.x;
    int l8 = t & 7, rgrp = t >> 3;

    float4 g4 = __ldg(&((const float4*)eg)[l8]);
    float4 b4 = __ldg(&((const float4*)eb)[l8]);
    float4 wb = __ldg(&((const float4*)Web)[l8]);
    float bb = __ldg(beb);

    #pragma unroll
    for (int pp = 0; pp < 12; pp++) {
        int j = pp * 32 + rgrp;
        float4 e = edge4[((long long)bi * Nt + j) * 8 + l8];
        float s = e.x + e.y + e.z + e.w;
        s += __shfl_xor_sync(0xffffffffu, s, 4);
        s += __shfl_xor_sync(0xffffffffu, s, 2);
        s += __shfl_xor_sync(0xffffffffu, s, 1);
        float mean = s * (1.0f / 32.0f);
        float4 d = make_float4(e.x - mean, e.y - mean, e.z - mean, e.w - mean);
        float vq = d.x*d.x + d.y*d.y + d.z*d.z + d.w*d.w;
        vq += __shfl_xor_sync(0xffffffffu, vq, 4);
        vq += __shfl_xor_sync(0xffffffffu, vq, 2);
        vq += __shfl_xor_sync(0xffffffffu, vq, 1);
        float inv = rsqrtf(vq * (1.0f / 32.0f) + 1e-5f);
        float4 ne;
        ne.x = d.x * inv * g4.x + b4.x;
        ne.y = d.y * inv * g4.y + b4.y;
        ne.z = d.z * inv * g4.z + b4.z;
        ne.w = d.w * inv * g4.w + b4.w;
        float pb = ne.x*wb.x + ne.y*wb.y + ne.z*wb.z + ne.w*wb.w;
        pb += __shfl_xor_sync(0xffffffffu, pb, 4);
        pb += __shfl_xor_sync(0xffffffffu, pb, 2);
        pb += __shfl_xor_sync(0xffffffffu, pb, 1);
        if (l8 == 0) sbias[j] = (pb + bb) * 0.70710678118654752f;
        ne.x = f2tf(ne.x); ne.y = f2tf(ne.y);
        ne.z = f2tf(ne.z); ne.w = f2tf(ne.w);
        *(float4*)&sB[j * LDBS + l8 * 4] = ne;
    }
    __syncthreads();

    int warp = t >> 5, lane = t & 31;
    float* sp = attn + (((size_t)(b * Ht + warp)) * Nt + i) * Nt;
    const unsigned char* mp = mask + (size_t)bi * Nt;
    float v[12];
    float mx = -INFINITY;
    #pragma unroll
    for (int r = 0; r < 12; r++) {
        int j = lane + r * 32;
        float s = sp[j] + sbias[j];
        if (mp[j]) s = -INFINITY;
        v[r] = s;
        mx = fmaxf(mx, s);
    }
    #pragma unroll
    for (int o = 16; o; o >>= 1) mx = fmaxf(mx, __shfl_xor_sync(0xffffffffu, mx, o));
    float sum = 0.0f;
    #pragma unroll
    for (int r = 0; r < 12; r++) { v[r] = __expf(v[r] - mx); sum += v[r]; }
    #pragma unroll
    for (int o = 16; o; o >>= 1) sum += __shfl_xor_sync(0xffffffffu, sum, o);
    float invs = 1.0f / sum;
    #pragma unroll
    for (int r = 0; r < 12; r++) {
        int j = lane + r * 32;
        float val = f2tf(v[r] * invs);
        sp[j] = val;
        sA[warp * LDAS + j] = val;
    }
    __syncthreads();

    if (warp < 4) {
        int g = lane >> 2, tig = lane & 3;
        int n0 = warp * 8;
        float acc[4] = {0.0f, 0.0f, 0.0f, 0.0f};
        #pragma unroll
        for (int k8 = 0; k8 < 48; k8++) {
            int kb = k8 * 8;
            uint32_t afr[4], bfr[2];
            afr[0] = __float_as_uint(sA[g * LDAS + kb + tig]);
            afr[1] = __float_as_uint(sA[(g + 8) * LDAS + kb + tig]);
            afr[2] = __float_as_uint(sA[g * LDAS + kb + tig + 4]);
            afr[3] = __float_as_uint(sA[(g + 8) * LDAS + kb + tig + 4]);
            bfr[0] = __float_as_uint(sB[(kb + tig) * LDBS + n0 + g]);
            bfr[1] = __float_as_uint(sB[(kb + tig + 4) * LDBS + n0 + g]);
            mma_tf32(acc, afr, bfr);
        }
        // write tf32-rounded so downstream x1 GEMM can skip cvt
        float2 o = make_float2(f2tf(acc[0]), f2tf(acc[1]));
        *(float2*)&cat[(size_t)bi * 768 + 512 + g * DEt + n0 + tig * 2] = o;
    }
}

// ---------------- launch ----------------
extern "C" void kernel_launch(void* const* d_in, const int* in_sizes, int n_in,
                              void* d_out, int out_size)
{
    const float* x      = (const float*)d_in[0];
    const float* edge   = (const float*)d_in[1];
    const unsigned char* mask = (const unsigned char*)d_in[2];
    const float* ln_a_g = (const float*)d_in[3];
    const float* ln_a_b = (const float*)d_in[4];
    const float* ln_e_g = (const float*)d_in[5];
    const float* ln_e_b = (const float*)d_in[6];
    const float* Wq = (const float*)d_in[7];   const float* bq = (const float*)d_in[8];
    const float* Wk = (const float*)d_in[9];   const float* bk = (const float*)d_in[10];
    const float* Wv = (const float*)d_in[11];  const float* bv = (const float*)d_in[12];
    const float* Wke = (const float*)d_in[13]; const float* bke = (const float*)d_in[14];
    const float* Web = (const float*)d_in[15]; const float* beb = (const float*)d_in[16];
    const float* Weo = (const float*)d_in[17]; const float* beo = (const float*)d_in[18];
    const float* Wo  = (const float*)d_in[19]; const float* bo  = (const float*)d_in[20];
    const float* ln_f_g = (const float*)d_in[21];
    const float* ln_f_b = (const float*)d_in[22];
    const float* W1 = (const float*)d_in[23];  const float* b1 = (const float*)d_in[24];
    const float* W2 = (const float*)d_in[25];  const float* b2 = (const float*)d_in[26];
    float* out = (float*)d_out;

    float* base;
    cudaGetSymbolAddress((void**)&base, g_scratch);
    float* nx    = base + OFF_NX;
    float* qkv   = base + OFF_QKV;
    float* attn  = base + OFF_ATTN;
    float* cat   = base + OFF_CAT;
    float* x1    = base + OFF_X1;
    float* nx2   = base + OFF_NX2;
    float* h1    = base + OFF_H1;
    float* Wqkv  = base + OFF_WQKV;
    float* bqkv  = base + OFF_BQKV;
    float* Wfold = base + OFF_WFOLD;
    float* Wcat  = base + OFF_WCAT;
    float* bcomb = base + OFF_BCOMB;
    float* W1t   = base + OFF_W1T;
    float* W2t   = base + OFF_W2T;

    auto GA  = gemm_tf32_kernel<128, 128, 64, 32, false, false>;
    auto GT  = gemm_tf32_kernel<128, 128, 64, 32, true,  false>;
    auto GV  = gemm_tf32_kernel<128, 64, 32, 32, false, false>;
    auto GS  = gemm_tf32_kernel<64, 64, 16, 32, false, true>;

    constexpr int SMEM_GA = 2 * (128 * 36 + 32 * 136) * 4;    // 71680
    constexpr int SMEM_GT = 2 * (128 * 36 + 128 * 36) * 4;    // 73728
    constexpr int SMEM_GV = 2 * (128 * 36 + 32 * 72) * 4;     // 55296
    constexpr int SMEM_GS = 2 * (64 * 36 + 32 * 72) * 4;      // 36864
    constexpr int SMEM_EA = (16 * 388 + 384 * 40 + 384) * 4;  // 87808
    cudaFuncSetAttribute(GA,  cudaFuncAttributeMaxDynamicSharedMemorySize, SMEM_GA);
    cudaFuncSetAttribute(GT,  cudaFuncAttributeMaxDynamicSharedMemorySize, SMEM_GT);
    cudaFuncSetAttribute(GV,  cudaFuncAttributeMaxDynamicSharedMemorySize, SMEM_GV);
    cudaFuncSetAttribute(GS,  cudaFuncAttributeMaxDynamicSharedMemorySize, SMEM_GS);
    cudaFuncSetAttribute(edge_attn_kernel, cudaFuncAttributeMaxDynamicSharedMemorySize, SMEM_EA);

    // 0. merged preproc (rounded weight packs) + split-K Wcomb + round Wcomb
    preproc_kernel<<<576, 256>>>(Wq, Wk, Wv, bq, bk, bv, Wo, bo, Wke, bke, Weo, beo,
                                 W1, W2, Wqkv, bqkv, Wcat, Wfold, bcomb, W1t, W2t);
    GS<<<dim3(Dt / 64, 4, 4), 256, SMEM_GS>>>(Wfold, Wo + (size_t)Dt * Dt,
        Wcat + (size_t)Dt * Dt, 128, Dt, Dt, Dt,
        4, 0, 128, 0, (long long)128 * Dt, 0, 0,
        1.0f, nullptr, nullptr, 0, 2, 0, 0);
    // round Wcat bottom (256x512 floats = 32768 float4) so x1 GEMM skips cvt
    round_tf_kernel<<<128, 256>>>((float4*)(Wcat + (size_t)Dt * Dt));

    // 1. LN(x), tf32-rounded
    ln512_kernel<<<BNr, 128>>>(x, ln_a_g, ln_a_b, nx, 1);

    // 2. fused qkv projection, outputs tf32-rounded
    dim3 gqkv(1536 / 128, BNr / 128, 1);
    GA<<<gqkv, 256, SMEM_GA>>>(nx, Wqkv, qkv, Dt, Dt, 1536, 1536,
        1, 0, 0, 0, 0, 0, 0, 1.0f, bqkv, nullptr, 0, 0, 0, 1);

    // 3. scores = alpha * Q @ K^T
    dim3 gsc(Nt / 128, Nt / 128, Bt * Ht);
    GT<<<gsc, 256, SMEM_GT>>>(qkv, qkv + 512, attn, DKt, 1536, 1536, Nt,
        Ht, (long long)Nt * 1536, 64, (long long)Nt * 1536, 64,
        (long long)Ht * NNt, (long long)NNt,
        0.08838834764831845f, nullptr, nullptr, 0, 0, 0, 0);

    // 4. fused edge LN + bias + softmax + ectx contraction (raw half rounded)
    edge_attn_kernel<<<BNr, 256, SMEM_EA>>>(attn, (const float4*)edge,
        ln_e_g, ln_e_b, Web, beb, mask, cat);

    // 5. ctx half of cat = attn @ V, output tf32-rounded
    dim3 gcx(1, Nt / 128, Bt * Ht);
    GV<<<gcx, 256, SMEM_GV>>>(attn, qkv + 1024, cat, Nt, Nt, 1536, 768,
        Ht, (long long)Ht * NNt, (long long)NNt, (long long)Nt * 1536, 64,
        (long long)Nt * 768, 64,
        1.0f, nullptr, nullptr, 0, 0, 0, 1);

    // 6. x1 = x + cat @ Wcat + bcomb (all operands pre-rounded -> cp.async path)
    dim3 gx1(Dt / 128, BNr / 128, 1);
    GA<<<gx1, 256, SMEM_GA>>>(cat, Wcat, x1, 768, 768, Dt, Dt,
        1, 0, 0, 0, 0, 0, 0, 1.0f, bcomb, x, Dt, 0, 0, 0);

    // 7. nx2 = LN(x1), tf32-rounded
    ln512_kernel<<<BNr, 128>>>(x1, ln_f_g, ln_f_b, nx2, 1);

    // 8. h1 = gelu(nx2 @ W1t + b1), tf32-rounded
    dim3 gf1(DFt / 128, BNr / 128, 1);
    GA<<<gf1, 256, SMEM_GA>>>(nx2, W1t, h1, Dt, Dt, DFt, DFt,
        1, 0, 0, 0, 0, 0, 0, 1.0f, b1, nullptr, 0, 0, 1, 1);

    // 9. out = x1 + h1 @ W2t + b2
    dim3 gf2(Dt / 128, BNr / 128, 1);
    GA<<<gf2, 256, SMEM_GA>>>(h1, W2t, out, DFt, DFt, Dt, Dt,
        1, 0, 0, 0, 0, 0, 0, 1.0f, b2, x1, Dt, 0, 0, 0);

    (void)in_sizes; (void)n_in; (void)out_size;
}